// round 2
// baseline (speedup 1.0000x reference)
#include <cuda_runtime.h>
#include <math.h>

#define NB 512      // batch
#define NT 20       // time
#define NOBJ 36
#define ND 2048
#define NEMB 300
#define NE 512
#define NHM 1024
#define NHO 256

constexpr int BT   = NB * NT;        // 10240
constexpr int KAM  = 832;            // E+EMB=812 padded to mult of 16
constexpr int KAO  = 1344;           // 2E+EMB=1324 padded
constexpr int GM4  = 4 * NHM;        // 4096
constexpr int GO4  = 4 * NHO;        // 1024
constexpr int LDW_M = NE + NEMB + ND;        // 2860
constexpr int LDW_O = 2 * NE + NEMB + ND;    // 3372

// ---------------- scratch layout (single __device__ arena) ----------------
constexpr size_t OFF_MASK = 0;
constexpr size_t OFF_MEAN = OFF_MASK + (size_t)NB * NOBJ;
constexpr size_t OFF_AM   = OFF_MEAN + (size_t)NB * ND;
constexpr size_t OFF_AO   = OFF_AM   + (size_t)BT * KAM;
constexpr size_t OFF_GM   = OFF_AO   + (size_t)BT * KAO;
constexpr size_t OFF_GO   = OFF_GM   + (size_t)BT * GM4;
constexpr size_t OFF_FM   = OFF_GO   + (size_t)BT * GO4;
constexpr size_t OFF_FO   = OFF_FM   + (size_t)NB * GM4;
constexpr size_t OFF_HM   = OFF_FO   + (size_t)NB * GO4;   // state h_m
constexpr size_t OFF_CM   = OFF_HM   + (size_t)NB * NHM;
constexpr size_t OFF_HO   = OFF_CM   + (size_t)NB * NHM;
constexpr size_t OFF_CO   = OFF_HO   + (size_t)NB * NHO;
constexpr size_t OFF_RM   = OFF_CO   + (size_t)NB * NHO;
constexpr size_t OFF_RO   = OFF_RM   + (size_t)NB * GM4;
constexpr size_t OFF_HMS  = OFF_RO   + (size_t)NB * GO4;   // all-step h_m
constexpr size_t OFF_HOS  = OFF_HMS  + (size_t)BT * NHM;
constexpr size_t OFF_OUTM = OFF_HOS  + (size_t)BT * NHO;
constexpr size_t OFF_OUTO = OFF_OUTM + (size_t)BT * 2 * NE;
constexpr size_t TOTAL    = OFF_OUTO + (size_t)BT * 2 * NE;

__device__ float d_scratch[TOTAL];

// ---------------- generic SGEMM:  C[M,N] = A[M,K] @ W[N,K]^T (+bias) ------
// Requires M%128==0, N%128==0, K%16==0; lda/ldw/ldc mult of 4; ptrs 16B-aligned.
#define BM 128
#define BN 128
#define BKK 16

__global__ __launch_bounds__(256) void gemm_nt(
    const float* __restrict__ A, int lda,
    const float* __restrict__ W, int ldw,
    float* __restrict__ C, int ldc,
    int M, int N, int K,
    const float* __restrict__ bias)
{
    __shared__ float As[BKK][BM + 4];
    __shared__ float Bs[BKK][BN + 4];

    const int tid = threadIdx.x;          // 0..255
    const int tx  = tid & 15;             // 0..15 -> n
    const int ty  = tid >> 4;             // 0..15 -> m
    const int bm  = blockIdx.y * BM;
    const int bn  = blockIdx.x * BN;

    float acc[8][8];
#pragma unroll
    for (int i = 0; i < 8; i++)
#pragma unroll
        for (int j = 0; j < 8; j++) acc[i][j] = 0.f;

    for (int k0 = 0; k0 < K; k0 += BKK) {
#pragma unroll
        for (int i = 0; i < 2; i++) {
            int v = tid + i * 256;            // 0..511
            int row = v >> 2;                 // 0..127
            int kq  = (v & 3) << 2;           // 0,4,8,12
            float4 a = *(const float4*)(A + (size_t)(bm + row) * lda + k0 + kq);
            As[kq + 0][row] = a.x; As[kq + 1][row] = a.y;
            As[kq + 2][row] = a.z; As[kq + 3][row] = a.w;
            float4 b = *(const float4*)(W + (size_t)(bn + row) * ldw + k0 + kq);
            Bs[kq + 0][row] = b.x; Bs[kq + 1][row] = b.y;
            Bs[kq + 2][row] = b.z; Bs[kq + 3][row] = b.w;
        }
        __syncthreads();

#pragma unroll
        for (int k = 0; k < BKK; k++) {
            float a[8], b[8];
            *(float4*)(a)     = *(const float4*)&As[k][ty * 8];
            *(float4*)(a + 4) = *(const float4*)&As[k][ty * 8 + 4];
            *(float4*)(b)     = *(const float4*)&Bs[k][tx * 8];
            *(float4*)(b + 4) = *(const float4*)&Bs[k][tx * 8 + 4];
#pragma unroll
            for (int i = 0; i < 8; i++)
#pragma unroll
                for (int j = 0; j < 8; j++) acc[i][j] = fmaf(a[i], b[j], acc[i][j]);
        }
        __syncthreads();
    }

    float bv[8];
#pragma unroll
    for (int j = 0; j < 8; j++) bv[j] = bias ? bias[bn + tx * 8 + j] : 0.f;

#pragma unroll
    for (int i = 0; i < 8; i++) {
        float* cp = C + (size_t)(bm + ty * 8 + i) * ldc + bn + tx * 8;
        float4 v0 = make_float4(acc[i][0] + bv[0], acc[i][1] + bv[1],
                                acc[i][2] + bv[2], acc[i][3] + bv[3]);
        float4 v1 = make_float4(acc[i][4] + bv[4], acc[i][5] + bv[5],
                                acc[i][6] + bv[6], acc[i][7] + bv[7]);
        *(float4*)(cp)     = v0;
        *(float4*)(cp + 4) = v1;
    }
}

// ---------------- small kernels ----------------
__global__ void objmask_kernel(const float* __restrict__ obj, float* __restrict__ mask)
{
    int bn = blockIdx.x;                     // 0..B*NOBJ-1
    const float* p = obj + (size_t)bn * ND;
    float s = 0.f;
    for (int d = threadIdx.x; d < ND; d += blockDim.x) s += fabsf(p[d]);
    __shared__ float sm[4];
    for (int o = 16; o; o >>= 1) s += __shfl_down_sync(0xffffffffu, s, o);
    if ((threadIdx.x & 31) == 0) sm[threadIdx.x >> 5] = s;
    __syncthreads();
    if (threadIdx.x == 0) {
        float v = sm[0] + sm[1] + sm[2] + sm[3];
        mask[bn] = v > 0.f ? 1.f : 0.f;
    }
}

__global__ void mean_kernel(const float* __restrict__ obj,
                            const float* __restrict__ mask,
                            float* __restrict__ mean)
{
    int idx = blockIdx.x * blockDim.x + threadIdx.x;   // B*D
    int b = idx >> 11;
    int d = idx & (ND - 1);
    const float* mb = mask + b * NOBJ;
    const float* ob = obj + ((size_t)b * NOBJ) * ND + d;
    float acc = 0.f, cnt = 0.f;
#pragma unroll 4
    for (int n = 0; n < NOBJ; n++) {
        float m = mb[n];
        cnt += m;
        acc += ob[(size_t)n * ND] * m;
    }
    mean[idx] = acc / fmaxf(cnt, 1e-9f);
}

__global__ void build_Am(const float* __restrict__ qzm, const int* __restrict__ x,
                         const float* __restrict__ emb, float* __restrict__ Am)
{
    int r = blockIdx.x;                  // b*T+t
    int t = r % NT;
    int b = r / NT;
    float* out = Am + (size_t)r * KAM;
    const float* z = qzm + ((size_t)b * NT + (t - 1)) * NE;   // valid only if t>0
    const float* e = emb + (size_t)x[r] * NEMB;
    for (int c = threadIdx.x; c < KAM; c += blockDim.x) {
        float v;
        if (c < NE)              v = (t == 0) ? 0.f : z[c];
        else if (c < NE + NEMB)  v = e[c - NE];
        else                     v = 0.f;
        out[c] = v;
    }
}

__global__ void build_Ao(const float* __restrict__ qzm, const float* __restrict__ qzo,
                         const int* __restrict__ x, const float* __restrict__ emb,
                         float* __restrict__ Ao)
{
    int r = blockIdx.x;
    int t = r % NT;
    int b = r / NT;
    float* out = Ao + (size_t)r * KAO;
    const float* zc = qzm + ((size_t)b * NT + t) * NE;
    const float* zp = qzo + ((size_t)b * NT + (t - 1)) * NE;
    const float* e  = emb + (size_t)x[r] * NEMB;
    for (int c = threadIdx.x; c < KAO; c += blockDim.x) {
        float v;
        if (c < NE)                    v = zc[c];
        else if (c < 2 * NE)           v = (t == 0) ? 0.f : zp[c - NE];
        else if (c < 2 * NE + NEMB)    v = e[c - 2 * NE];
        else                           v = 0.f;
        out[c] = v;
    }
}

__global__ void zero_state(float* hm, float* cm, float* ho, float* co)
{
    int idx = blockIdx.x * blockDim.x + threadIdx.x;
    if (idx < NB * NHM) { hm[idx] = 0.f; cm[idx] = 0.f; }
    if (idx < NB * NHO) { ho[idx] = 0.f; co[idx] = 0.f; }
}

__device__ __forceinline__ float sigmoidf(float v) { return 1.f / (1.f + __expf(-v)); }

template <int H>
__global__ void cell_kernel(const float* __restrict__ G, const float* __restrict__ F,
                            const float* __restrict__ R, float* __restrict__ h,
                            float* __restrict__ c, float* __restrict__ Hout, int t)
{
    int idx = blockIdx.x * blockDim.x + threadIdx.x;   // B*H
    int b = idx / H;
    int j = idx - b * H;
    size_t gb = ((size_t)(b * NT + t)) * (4 * H) + j;
    size_t fb = (size_t)b * (4 * H) + j;
    float gi = G[gb]         + F[fb]         + R[fb];
    float gf = G[gb + H]     + F[fb + H]     + R[fb + H];
    float gg = G[gb + 2 * H] + F[fb + 2 * H] + R[fb + 2 * H];
    float go = G[gb + 3 * H] + F[fb + 3 * H] + R[fb + 3 * H];
    float cn = sigmoidf(gf) * c[idx] + sigmoidf(gi) * tanhf(gg);
    float hn = sigmoidf(go) * tanhf(cn);
    c[idx] = cn;
    h[idx] = hn;
    Hout[((size_t)(b * NT + t)) * H + j] = hn;
}

__global__ void kl_kernel(const float* __restrict__ outm, const float* __restrict__ outo,
                          const float* __restrict__ qmm, const float* __restrict__ qlm,
                          const float* __restrict__ qmo, const float* __restrict__ qlo,
                          const int* __restrict__ x, float* __restrict__ out)
{
    int b = blockIdx.x;
    float acc = 0.f;
    for (int i = threadIdx.x; i < NT * NE; i += blockDim.x) {
        int t = i / NE;
        int e = i - t * NE;
        int tok = x[b * NT + t];
        if (tok == 0 || tok == 2) continue;
        size_t ro = (size_t)b * NT + t;
        size_t po = ro * (2 * NE);
        size_t qo = ro * NE + e;
        float pm = outm[po + e], pl = outm[po + NE + e];
        float qm = qmm[qo],      ql = qlm[qo];
        float dm = qm - pm;
        acc += 0.5f * (pl - ql) + (expf(ql) + dm * dm) / (2.f * expf(pl)) - 0.5f;
        pm = outo[po + e]; pl = outo[po + NE + e];
        qm = qmo[qo];      ql = qlo[qo];
        dm = qm - pm;
        acc += 0.5f * (pl - ql) + (expf(ql) + dm * dm) / (2.f * expf(pl)) - 0.5f;
    }
    __shared__ float sm[256];
    sm[threadIdx.x] = acc;
    __syncthreads();
    for (int s = 128; s; s >>= 1) {
        if (threadIdx.x < s) sm[threadIdx.x] += sm[threadIdx.x + s];
        __syncthreads();
    }
    if (threadIdx.x == 0) out[b] = sm[0];
}

// ---------------- host ----------------
extern "C" void kernel_launch(void* const* d_in, const int* in_sizes, int n_in,
                              void* d_out, int out_size)
{
    const float* obj_enc  = (const float*)d_in[0];
    const int*   x        = (const int*)  d_in[1];
    const float* qmm      = (const float*)d_in[2];
    const float* qlm      = (const float*)d_in[3];
    const float* qzm      = (const float*)d_in[4];
    const float* qmo      = (const float*)d_in[5];
    const float* qlo      = (const float*)d_in[6];
    const float* qzo      = (const float*)d_in[7];
    const float* emd_W    = (const float*)d_in[8];
    const float* W_ih_m   = (const float*)d_in[9];
    const float* W_hh_m   = (const float*)d_in[10];
    const float* b_m      = (const float*)d_in[11];
    const float* W_ih_o   = (const float*)d_in[12];
    const float* W_hh_o   = (const float*)d_in[13];
    const float* b_o      = (const float*)d_in[14];
    const float* fc_m_W   = (const float*)d_in[15];
    const float* fc_m_b   = (const float*)d_in[16];
    const float* fc_o_W   = (const float*)d_in[17];
    const float* fc_o_b   = (const float*)d_in[18];
    float* out = (float*)d_out;

    float* s = nullptr;
    cudaGetSymbolAddress((void**)&s, d_scratch);

    float* pMask = s + OFF_MASK;
    float* pMean = s + OFF_MEAN;
    float* pAm   = s + OFF_AM;
    float* pAo   = s + OFF_AO;
    float* pGm   = s + OFF_GM;
    float* pGo   = s + OFF_GO;
    float* pFm   = s + OFF_FM;
    float* pFo   = s + OFF_FO;
    float* phm   = s + OFF_HM;
    float* pcm   = s + OFF_CM;
    float* pho   = s + OFF_HO;
    float* pco   = s + OFF_CO;
    float* pRm   = s + OFF_RM;
    float* pRo   = s + OFF_RO;
    float* pHms  = s + OFF_HMS;
    float* pHos  = s + OFF_HOS;
    float* pOutm = s + OFF_OUTM;
    float* pOuto = s + OFF_OUTO;

    // 1) object mask + mean image features
    objmask_kernel<<<NB * NOBJ, 128>>>(obj_enc, pMask);
    mean_kernel<<<(NB * ND) / 256, 256>>>(obj_enc, pMask, pMean);

    // 2) build batched LSTM input matrices (padded K)
    build_Am<<<BT, 256>>>(qzm, x, emd_W, pAm);
    build_Ao<<<BT, 256>>>(qzm, qzo, x, emd_W, pAo);

    // 3) precompute input-to-hidden parts
    //    G = [zprev|xemb] @ W_ih[:, :K]^T + b   (time-varying part)
    gemm_nt<<<dim3(GM4 / BN, BT / BM), 256>>>(pAm, KAM, W_ih_m, LDW_M, pGm, GM4, BT, GM4, KAM, b_m);
    gemm_nt<<<dim3(GO4 / BN, BT / BM), 256>>>(pAo, KAO, W_ih_o, LDW_O, pGo, GO4, BT, GO4, KAO, b_o);
    //    F = meanimfeats @ W_ih[:, feat_cols]^T   (time-invariant part, once per b)
    gemm_nt<<<dim3(GM4 / BN, NB / BM), 256>>>(pMean, ND, W_ih_m + (NE + NEMB), LDW_M, pFm, GM4, NB, GM4, ND, nullptr);
    gemm_nt<<<dim3(GO4 / BN, NB / BM), 256>>>(pMean, ND, W_ih_o + (2 * NE + NEMB), LDW_O, pFo, GO4, NB, GO4, ND, nullptr);

    // 4) init state
    zero_state<<<(NB * NHM + 255) / 256, 256>>>(phm, pcm, pho, pco);

    // 5) sequential recurrence (only h @ W_hh is serialized)
    for (int t = 0; t < NT; t++) {
        gemm_nt<<<dim3(GM4 / BN, NB / BM), 256>>>(phm, NHM, W_hh_m, NHM, pRm, GM4, NB, GM4, NHM, nullptr);
        cell_kernel<NHM><<<(NB * NHM) / 256, 256>>>(pGm, pFm, pRm, phm, pcm, pHms, t);
        gemm_nt<<<dim3(GO4 / BN, NB / BM), 256>>>(pho, NHO, W_hh_o, NHO, pRo, GO4, NB, GO4, NHO, nullptr);
        cell_kernel<NHO><<<(NB * NHO) / 256, 256>>>(pGo, pFo, pRo, pho, pco, pHos, t);
    }

    // 6) output FCs (batched over B*T)
    gemm_nt<<<dim3((2 * NE) / BN, BT / BM), 256>>>(pHms, NHM, fc_m_W, NHM, pOutm, 2 * NE, BT, 2 * NE, NHM, fc_m_b);
    gemm_nt<<<dim3((2 * NE) / BN, BT / BM), 256>>>(pHos, NHO, fc_o_W, NHO, pOuto, 2 * NE, BT, 2 * NE, NHO, fc_o_b);

    // 7) KL reduction
    kl_kernel<<<NB, 256>>>(pOutm, pOuto, qmm, qlm, qmo, qlo, x, out);
}

// round 4
// speedup vs baseline: 3.6015x; 3.6015x over previous
#include <cuda_runtime.h>
#include <math.h>

#define NB 512      // batch
#define NT 20       // time
#define NOBJ 36
#define ND 2048
#define NEMB 300
#define NE 512
#define NHM 1024
#define NHO 256

constexpr int BT   = NB * NT;        // 10240
constexpr int KAM  = 832;            // E+EMB=812 padded to mult of 32
constexpr int KAO  = 1344;           // 2E+EMB=1324 padded to mult of 32
constexpr int GM4  = 4 * NHM;        // 4096
constexpr int GO4  = 4 * NHO;        // 1024
constexpr int LDW_M = NE + NEMB + ND;        // 2860
constexpr int LDW_O = 2 * NE + NEMB + ND;    // 3372

// ---------------- scratch layout (single __device__ arena) ----------------
constexpr size_t OFF_MASK = 0;
constexpr size_t OFF_MEAN = OFF_MASK + (size_t)NB * NOBJ;
constexpr size_t OFF_AM   = OFF_MEAN + (size_t)NB * ND;
constexpr size_t OFF_AO   = OFF_AM   + (size_t)BT * KAM;
constexpr size_t OFF_GM   = OFF_AO   + (size_t)BT * KAO;
constexpr size_t OFF_GO   = OFF_GM   + (size_t)BT * GM4;
constexpr size_t OFF_FM   = OFF_GO   + (size_t)BT * GO4;
constexpr size_t OFF_FO   = OFF_FM   + (size_t)NB * GM4;
constexpr size_t OFF_HM   = OFF_FO   + (size_t)NB * GO4;   // state h_m
constexpr size_t OFF_CM   = OFF_HM   + (size_t)NB * NHM;
constexpr size_t OFF_HO   = OFF_CM   + (size_t)NB * NHM;
constexpr size_t OFF_CO   = OFF_HO   + (size_t)NB * NHO;
constexpr size_t OFF_RM   = OFF_CO   + (size_t)NB * NHO;
constexpr size_t OFF_RO   = OFF_RM   + (size_t)NB * GM4;
constexpr size_t OFF_HMS  = OFF_RO   + (size_t)NB * GO4;   // all-step h_m
constexpr size_t OFF_HOS  = OFF_HMS  + (size_t)BT * NHM;
constexpr size_t OFF_OUTM = OFF_HOS  + (size_t)BT * NHO;
constexpr size_t OFF_OUTO = OFF_OUTM + (size_t)BT * 2 * NE;
constexpr size_t TOTAL    = OFF_OUTO + (size_t)BT * 2 * NE;

__device__ float d_scratch[TOTAL];

// =====================================================================
// tf32 tensor-core GEMM:  C[M,N] = A[M,K] @ W[N,K]^T (+bias)
// Block 128x128, K-tile 32, 8 warps of 64x32, mma.m16n8k8.tf32.
// Requires M%128==0 (gridDim.y), N%128==0 (gridDim.x), K%32==0,
// lda/ldw/ldc multiples of 4, all base pointers 16B aligned.
//
// Smem is stored in "fragment-major" reg-planes:
//   A: 4 planes (a0..a3). Within a plane, block (im,ik) of 32 lanes,
//      padded stride 33 so bank = (4*im+ik + lane) % 32 (kills conflicts).
//   B: 2 planes (b0,b1), blocks (jn,ik) of 32 lanes, stride 33.
// Fragment loads are consecutive-lane LDS.32 -> conflict-free.
// =====================================================================
#define APLANE 1056   // 8 m-tiles * 4 ik * 33
#define BPLANE 2112   // 16 n-tiles * 4 ik * 33

__device__ __forceinline__ unsigned f2tf32(float f) {
    unsigned u;
    asm("cvt.rna.tf32.f32 %0, %1;" : "=r"(u) : "f"(f));
    return u;
}

__device__ __forceinline__ void mma_tf32(float* d, const unsigned* a, const unsigned* b) {
    asm volatile(
        "mma.sync.aligned.m16n8k8.row.col.f32.tf32.tf32.f32 "
        "{%0,%1,%2,%3}, {%4,%5,%6,%7}, {%8,%9}, {%0,%1,%2,%3};"
        : "+f"(d[0]), "+f"(d[1]), "+f"(d[2]), "+f"(d[3])
        : "r"(a[0]), "r"(a[1]), "r"(a[2]), "r"(a[3]), "r"(b[0]), "r"(b[1]));
}

__global__ __launch_bounds__(256, 1) void gemm_tf32(
    const float* __restrict__ A, int lda,
    const float* __restrict__ W, int ldw,
    float* __restrict__ C, int ldc,
    int K, const float* __restrict__ bias)
{
    __shared__ float As[4 * APLANE];
    __shared__ float Bs[2 * BPLANE];

    const int tid  = threadIdx.x;
    const int lane = tid & 31;
    const int w    = tid >> 5;            // 0..7
    const int wm   = w & 1;               // 2 warps along M
    const int wn   = w >> 1;              // 4 warps along N
    const long bm  = (long)blockIdx.y * 128;
    const long bn  = (long)blockIdx.x * 128;

    float acc[4][4][4];
#pragma unroll
    for (int i = 0; i < 4; i++)
#pragma unroll
        for (int j = 0; j < 4; j++)
#pragma unroll
            for (int r = 0; r < 4; r++) acc[i][j][r] = 0.f;

    // per-thread fill coordinates (4 float4 per operand per k-tile)
    // v = tid + q*256 : row = v>>3 (0..127), f4col = v&7 (k = f4col*4..+3)
    float4 sa[4], sb[4];

#pragma unroll
    for (int q = 0; q < 4; q++) {
        int v = tid + q * 256;
        int row = v >> 3, f4 = v & 7;
        sa[q] = *(const float4*)(A + (bm + row) * (long)lda + f4 * 4);
        sb[q] = *(const float4*)(W + (bn + row) * (long)ldw + f4 * 4);
    }

    for (int k0 = 0; k0 < K; k0 += 32) {
        // ---- scatter staged regs into fragment-major smem (with tf32 cvt) ----
#pragma unroll
        for (int q = 0; q < 4; q++) {
            int v = tid + q * 256;
            int row = v >> 3, f4 = v & 7;
            // A: im = row>>4, r = row&15, g=r&7, hi=r>>3; ik=f4>>1, chalf=f4&1
            {
                int im = row >> 4, r = row & 15;
                int g = r & 7, hi = r >> 3;
                int ik = f4 >> 1, chalf = f4 & 1;
                float* pl = As + (hi + 2 * chalf) * APLANE + (im * 4 + ik) * 33 + g * 4;
                pl[0] = __uint_as_float(f2tf32(sa[q].x));
                pl[1] = __uint_as_float(f2tf32(sa[q].y));
                pl[2] = __uint_as_float(f2tf32(sa[q].z));
                pl[3] = __uint_as_float(f2tf32(sa[q].w));
            }
            // B: jn = row>>3, n8 = row&7; ik=f4>>1, reg=f4&1
            {
                int jn = row >> 3, n8 = row & 7;
                int ik = f4 >> 1, reg = f4 & 1;
                float* pl = Bs + reg * BPLANE + (jn * 4 + ik) * 33 + n8 * 4;
                pl[0] = __uint_as_float(f2tf32(sb[q].x));
                pl[1] = __uint_as_float(f2tf32(sb[q].y));
                pl[2] = __uint_as_float(f2tf32(sb[q].z));
                pl[3] = __uint_as_float(f2tf32(sb[q].w));
            }
        }
        __syncthreads();

        // ---- prefetch next k-tile into registers (LDG overlaps mma) ----
        if (k0 + 32 < K) {
#pragma unroll
            for (int q = 0; q < 4; q++) {
                int v = tid + q * 256;
                int row = v >> 3, f4 = v & 7;
                sa[q] = *(const float4*)(A + (bm + row) * (long)lda + (k0 + 32) + f4 * 4);
                sb[q] = *(const float4*)(W + (bn + row) * (long)ldw + (k0 + 32) + f4 * 4);
            }
        }

        // ---- compute 4 k8 sub-steps ----
#pragma unroll
        for (int ik = 0; ik < 4; ik++) {
            unsigned af[4][4], bf[4][2];
#pragma unroll
            for (int il = 0; il < 4; il++) {
                int blk = ((wm * 4 + il) * 4 + ik) * 33 + lane;
                af[il][0] = __float_as_uint(As[0 * APLANE + blk]);
                af[il][1] = __float_as_uint(As[1 * APLANE + blk]);
                af[il][2] = __float_as_uint(As[2 * APLANE + blk]);
                af[il][3] = __float_as_uint(As[3 * APLANE + blk]);
            }
#pragma unroll
            for (int jl = 0; jl < 4; jl++) {
                int blk = ((wn * 4 + jl) * 4 + ik) * 33 + lane;
                bf[jl][0] = __float_as_uint(Bs[0 * BPLANE + blk]);
                bf[jl][1] = __float_as_uint(Bs[1 * BPLANE + blk]);
            }
#pragma unroll
            for (int il = 0; il < 4; il++)
#pragma unroll
                for (int jl = 0; jl < 4; jl++)
                    mma_tf32(acc[il][jl], af[il], bf[jl]);
        }
        __syncthreads();
    }

    // ---- epilogue ----
    const int g = lane >> 2;
    const int cpair = (lane & 3) * 2;
#pragma unroll
    for (int jl = 0; jl < 4; jl++) {
        long col = bn + wn * 32 + jl * 8 + cpair;
        float bv0 = 0.f, bv1 = 0.f;
        if (bias) { bv0 = bias[col]; bv1 = bias[col + 1]; }
#pragma unroll
        for (int il = 0; il < 4; il++) {
            long row0 = bm + wm * 64 + il * 16 + g;
            float2 v0 = make_float2(acc[il][jl][0] + bv0, acc[il][jl][1] + bv1);
            float2 v1 = make_float2(acc[il][jl][2] + bv0, acc[il][jl][3] + bv1);
            *(float2*)(C + row0 * (long)ldc + col)       = v0;
            *(float2*)(C + (row0 + 8) * (long)ldc + col) = v1;
        }
    }
}

// ---------------- small kernels ----------------
__global__ void objmask_kernel(const float* __restrict__ obj, float* __restrict__ mask)
{
    int bn = blockIdx.x;                     // 0..B*NOBJ-1
    const float* p = obj + (size_t)bn * ND;
    float s = 0.f;
    for (int d = threadIdx.x; d < ND; d += blockDim.x) s += fabsf(p[d]);
    __shared__ float sm[4];
    for (int o = 16; o; o >>= 1) s += __shfl_down_sync(0xffffffffu, s, o);
    if ((threadIdx.x & 31) == 0) sm[threadIdx.x >> 5] = s;
    __syncthreads();
    if (threadIdx.x == 0) {
        float v = sm[0] + sm[1] + sm[2] + sm[3];
        mask[bn] = v > 0.f ? 1.f : 0.f;
    }
}

__global__ void mean_kernel(const float* __restrict__ obj,
                            const float* __restrict__ mask,
                            float* __restrict__ mean)
{
    int idx = blockIdx.x * blockDim.x + threadIdx.x;   // B*D
    int b = idx >> 11;
    int d = idx & (ND - 1);
    const float* mb = mask + b * NOBJ;
    const float* ob = obj + ((size_t)b * NOBJ) * ND + d;
    float acc = 0.f, cnt = 0.f;
#pragma unroll 4
    for (int n = 0; n < NOBJ; n++) {
        float m = mb[n];
        cnt += m;
        acc += ob[(size_t)n * ND] * m;
    }
    mean[idx] = acc / fmaxf(cnt, 1e-9f);
}

__global__ void build_Am(const float* __restrict__ qzm, const int* __restrict__ x,
                         const float* __restrict__ emb, float* __restrict__ Am)
{
    int r = blockIdx.x;                  // b*T+t
    int t = r % NT;
    int b = r / NT;
    float* out = Am + (size_t)r * KAM;
    const float* z = qzm + ((size_t)b * NT + (t - 1)) * NE;   // valid only if t>0
    const float* e = emb + (size_t)x[r] * NEMB;
    for (int c = threadIdx.x; c < KAM; c += blockDim.x) {
        float v;
        if (c < NE)              v = (t == 0) ? 0.f : z[c];
        else if (c < NE + NEMB)  v = e[c - NE];
        else                     v = 0.f;
        out[c] = v;
    }
}

__global__ void build_Ao(const float* __restrict__ qzm, const float* __restrict__ qzo,
                         const int* __restrict__ x, const float* __restrict__ emb,
                         float* __restrict__ Ao)
{
    int r = blockIdx.x;
    int t = r % NT;
    int b = r / NT;
    float* out = Ao + (size_t)r * KAO;
    const float* zc = qzm + ((size_t)b * NT + t) * NE;
    const float* zp = qzo + ((size_t)b * NT + (t - 1)) * NE;
    const float* e  = emb + (size_t)x[r] * NEMB;
    for (int c = threadIdx.x; c < KAO; c += blockDim.x) {
        float v;
        if (c < NE)                    v = zc[c];
        else if (c < 2 * NE)           v = (t == 0) ? 0.f : zp[c - NE];
        else if (c < 2 * NE + NEMB)    v = e[c - 2 * NE];
        else                           v = 0.f;
        out[c] = v;
    }
}

__global__ void zero_state(float* hm, float* cm, float* ho, float* co)
{
    int idx = blockIdx.x * blockDim.x + threadIdx.x;
    if (idx < NB * NHM) { hm[idx] = 0.f; cm[idx] = 0.f; }
    if (idx < NB * NHO) { ho[idx] = 0.f; co[idx] = 0.f; }
}

__device__ __forceinline__ float sigmoidf(float v) { return 1.f / (1.f + __expf(-v)); }

template <int H>
__global__ void cell_kernel(const float* __restrict__ G, const float* __restrict__ F,
                            const float* __restrict__ R, float* __restrict__ h,
                            float* __restrict__ c, float* __restrict__ Hout, int t)
{
    int idx = blockIdx.x * blockDim.x + threadIdx.x;   // B*H
    int b = idx / H;
    int j = idx - b * H;
    size_t gb = ((size_t)(b * NT + t)) * (4 * H) + j;
    size_t fb = (size_t)b * (4 * H) + j;
    float gi = G[gb]         + F[fb]         + R[fb];
    float gf = G[gb + H]     + F[fb + H]     + R[fb + H];
    float gg = G[gb + 2 * H] + F[fb + 2 * H] + R[fb + 2 * H];
    float go = G[gb + 3 * H] + F[fb + 3 * H] + R[fb + 3 * H];
    float cn = sigmoidf(gf) * c[idx] + sigmoidf(gi) * tanhf(gg);
    float hn = sigmoidf(go) * tanhf(cn);
    c[idx] = cn;
    h[idx] = hn;
    Hout[((size_t)(b * NT + t)) * H + j] = hn;
}

__global__ void kl_kernel(const float* __restrict__ outm, const float* __restrict__ outo,
                          const float* __restrict__ qmm, const float* __restrict__ qlm,
                          const float* __restrict__ qmo, const float* __restrict__ qlo,
                          const int* __restrict__ x, float* __restrict__ out)
{
    int b = blockIdx.x;
    float acc = 0.f;
    for (int i = threadIdx.x; i < NT * NE; i += blockDim.x) {
        int t = i / NE;
        int e = i - t * NE;
        int tok = x[b * NT + t];
        if (tok == 0 || tok == 2) continue;
        size_t ro = (size_t)b * NT + t;
        size_t po = ro * (2 * NE);
        size_t qo = ro * NE + e;
        float pm = outm[po + e], pl = outm[po + NE + e];
        float qm = qmm[qo],      ql = qlm[qo];
        float dm = qm - pm;
        acc += 0.5f * (pl - ql) + (expf(ql) + dm * dm) / (2.f * expf(pl)) - 0.5f;
        pm = outo[po + e]; pl = outo[po + NE + e];
        qm = qmo[qo];      ql = qlo[qo];
        dm = qm - pm;
        acc += 0.5f * (pl - ql) + (expf(ql) + dm * dm) / (2.f * expf(pl)) - 0.5f;
    }
    __shared__ float sm[256];
    sm[threadIdx.x] = acc;
    __syncthreads();
    for (int s = 128; s; s >>= 1) {
        if (threadIdx.x < s) sm[threadIdx.x] += sm[threadIdx.x + s];
        __syncthreads();
    }
    if (threadIdx.x == 0) out[b] = sm[0];
}

// ---------------- host ----------------
extern "C" void kernel_launch(void* const* d_in, const int* in_sizes, int n_in,
                              void* d_out, int out_size)
{
    const float* obj_enc  = (const float*)d_in[0];
    const int*   x        = (const int*)  d_in[1];
    const float* qmm      = (const float*)d_in[2];
    const float* qlm      = (const float*)d_in[3];
    const float* qzm      = (const float*)d_in[4];
    const float* qmo      = (const float*)d_in[5];
    const float* qlo      = (const float*)d_in[6];
    const float* qzo      = (const float*)d_in[7];
    const float* emd_W    = (const float*)d_in[8];
    const float* W_ih_m   = (const float*)d_in[9];
    const float* W_hh_m   = (const float*)d_in[10];
    const float* b_m      = (const float*)d_in[11];
    const float* W_ih_o   = (const float*)d_in[12];
    const float* W_hh_o   = (const float*)d_in[13];
    const float* b_o      = (const float*)d_in[14];
    const float* fc_m_W   = (const float*)d_in[15];
    const float* fc_m_b   = (const float*)d_in[16];
    const float* fc_o_W   = (const float*)d_in[17];
    const float* fc_o_b   = (const float*)d_in[18];
    float* out = (float*)d_out;

    float* s = nullptr;
    cudaGetSymbolAddress((void**)&s, d_scratch);

    float* pMask = s + OFF_MASK;
    float* pMean = s + OFF_MEAN;
    float* pAm   = s + OFF_AM;
    float* pAo   = s + OFF_AO;
    float* pGm   = s + OFF_GM;
    float* pGo   = s + OFF_GO;
    float* pFm   = s + OFF_FM;
    float* pFo   = s + OFF_FO;
    float* phm   = s + OFF_HM;
    float* pcm   = s + OFF_CM;
    float* pho   = s + OFF_HO;
    float* pco   = s + OFF_CO;
    float* pRm   = s + OFF_RM;
    float* pRo   = s + OFF_RO;
    float* pHms  = s + OFF_HMS;
    float* pHos  = s + OFF_HOS;
    float* pOutm = s + OFF_OUTM;
    float* pOuto = s + OFF_OUTO;

    // 1) object mask + mean image features
    objmask_kernel<<<NB * NOBJ, 128>>>(obj_enc, pMask);
    mean_kernel<<<(NB * ND) / 256, 256>>>(obj_enc, pMask, pMean);

    // 2) build batched LSTM input matrices (padded K)
    build_Am<<<BT, 256>>>(qzm, x, emd_W, pAm);
    build_Ao<<<BT, 256>>>(qzm, qzo, x, emd_W, pAo);

    // 3) precompute input-to-hidden parts (tensor cores, tf32)
    gemm_tf32<<<dim3(GM4 / 128, BT / 128), 256>>>(pAm, KAM, W_ih_m, LDW_M, pGm, GM4, KAM, b_m);
    gemm_tf32<<<dim3(GO4 / 128, BT / 128), 256>>>(pAo, KAO, W_ih_o, LDW_O, pGo, GO4, KAO, b_o);
    gemm_tf32<<<dim3(GM4 / 128, NB / 128), 256>>>(pMean, ND, W_ih_m + (NE + NEMB), LDW_M, pFm, GM4, ND, nullptr);
    gemm_tf32<<<dim3(GO4 / 128, NB / 128), 256>>>(pMean, ND, W_ih_o + (2 * NE + NEMB), LDW_O, pFo, GO4, ND, nullptr);

    // 4) init state
    zero_state<<<(NB * NHM + 255) / 256, 256>>>(phm, pcm, pho, pco);

    // 5) sequential recurrence (only h @ W_hh is serialized)
    for (int t = 0; t < NT; t++) {
        gemm_tf32<<<dim3(GM4 / 128, NB / 128), 256>>>(phm, NHM, W_hh_m, NHM, pRm, GM4, NHM, nullptr);
        cell_kernel<NHM><<<(NB * NHM) / 256, 256>>>(pGm, pFm, pRm, phm, pcm, pHms, t);
        gemm_tf32<<<dim3(GO4 / 128, NB / 128), 256>>>(pho, NHO, W_hh_o, NHO, pRo, GO4, NHO, nullptr);
        cell_kernel<NHO><<<(NB * NHO) / 256, 256>>>(pGo, pFo, pRo, pho, pco, pHos, t);
    }

    // 6) output FCs (batched over B*T)
    gemm_tf32<<<dim3((2 * NE) / 128, BT / 128), 256>>>(pHms, NHM, fc_m_W, NHM, pOutm, 2 * NE, NHM, fc_m_b);
    gemm_tf32<<<dim3((2 * NE) / 128, BT / 128), 256>>>(pHos, NHO, fc_o_W, NHO, pOuto, 2 * NE, NHO, fc_o_b);

    // 7) KL reduction
    kl_kernel<<<NB, 256>>>(pOutm, pOuto, qmm, qlm, qmo, qlo, x, out);
}